// round 16
// baseline (speedup 1.0000x reference)
#include <cuda_runtime.h>

// SheafLoss: B=4 T=1024 P=16 D=64 R=32 K=64, TAU=1
// d_in[0]=m (B,T,P,D) f32, d_in[1]=w (B,T,P) f32,
// d_in[2]=p (B,T,P,K) f32, d_in[3]=patch_centers (R,D) f32
// out: scalar f32
//
// Single persistent kernel: each CTA derives omega/cn/hs privately from the
// centers tile (no setup launch). Last-finished CTA writes the result and
// resets the accumulators for the next graph replay.

#define BT    4096
#define P_    16
#define D_    64
#define R_    32
#define K_    64
#define GRID_ 912          // 152 SMs x 6 CTAs: one persistent wave
#define LN2   0.6931471805599453f
#define TWO_LOG2E 2.8853900817779268f   // 2*log2(e)
#define LOG2E 1.4426950408889634f

typedef unsigned long long u64;

__device__ double g_acc = 0.0;
__device__ unsigned int g_done = 0u;

__device__ __forceinline__ void cp_async16(unsigned saddr, const void* gaddr) {
    asm volatile("cp.async.ca.shared.global [%0], [%1], 16;" :: "r"(saddr), "l"(gaddr));
}
__device__ __forceinline__ void cp_commit() {
    asm volatile("cp.async.commit_group;");
}
__device__ __forceinline__ u64 pk2(float x, float y) {
    u64 r; asm("mov.b64 %0, {%1, %2};" : "=l"(r) : "f"(x), "f"(y)); return r;
}
__device__ __forceinline__ void upk2(u64 v, float& x, float& y) {
    asm("mov.b64 {%0, %1}, %2;" : "=f"(x), "=f"(y) : "l"(v));
}
__device__ __forceinline__ u64 add2(u64 a, u64 b) {
    u64 r; asm("add.rn.f32x2 %0, %1, %2;" : "=l"(r) : "l"(a), "l"(b)); return r;
}
__device__ __forceinline__ float ex2f(float x) {
    float r; asm("ex2.approx.ftz.f32 %0, %1;" : "=f"(r) : "f"(x)); return r;
}

// ---------------------------------------------------------------------------
// Main: persistent grid (912 CTAs), grid-stride over tiles, 256 threads,
// 6 CTAs/SM, double-buffered m/p. Lane owns k-slice (2l, 2l+1); warp rows
// {w, 15-w, 16+w, 31-w}; omega rows computed per-CTA, register-resident.
// Algebra: s_pb holds p_bar + 1e-8. With q = pb'_r + pb'_s:
//   sum_k m*log2(m+eps) = 0.5*sum q*log2 q - 0.5*(S'_r + S'_s)
// pair loop accumulates om * sum q*log2 q per-lane; rows carry
// hs_r * sum_lane pb'*(log2 pb' + 1). loss(log2) = 0.5*(eacc - lacc) * LN2.
// ---------------------------------------------------------------------------
__global__ void __launch_bounds__(256, 6) sheaf_kernel(
    const float* __restrict__ gm,
    const float* __restrict__ gw,
    const float* __restrict__ gp,
    const float* __restrict__ gc,
    float* __restrict__ gout)
{
    __shared__ float  s_c[R_][68];        // centers row-major, 16B rows
    __shared__ float4 s_m[2][256];        // double-buffered m tile
    __shared__ float4 s_p[2][256];        // double-buffered p tile
    __shared__ float  s_w[2][P_];
    __shared__ float  s_sm[P_][R_ + 1];
    __shared__ float2 s_pb[R_][R_];       // [r][lane] = (pb'[2l], pb'[2l+1])
    __shared__ float  s_hs[R_];
    __shared__ float  s_red[8];

    const int tid  = threadIdx.x;
    const int lane = tid & 31;
    const int wid  = tid >> 5;

    const int r0 = wid, r1 = 15 - wid, r2 = 16 + wid, r3 = 31 - wid;
    const int rows[4] = { r0, r1, r2, r3 };

    // ---- per-CTA init: centers + first-tile prefetch ----
    {
        const int bt = blockIdx.x;
        unsigned a = (unsigned)__cvta_generic_to_shared(&s_m[0][tid]);
        unsigned b = (unsigned)__cvta_generic_to_shared(&s_p[0][tid]);
        cp_async16(a, (const float4*)(gm + (size_t)bt * 1024) + tid);
        cp_async16(b, (const float4*)(gp + (size_t)bt * 1024) + tid);
        cp_commit();
    }
    for (int i = tid; i < R_ * D_; i += 256) s_c[i >> 6][i & 63] = gc[i];
    float pw = (tid < P_) ? gw[(size_t)blockIdx.x * P_ + tid] : 0.f;
    __syncthreads();   // s_c ready

    // per-lane |c_lane|^2 (used in step1 where lane = r), pre-scaled by log2e
    float cn2;
    {
        float cnl = 0.f;
#pragma unroll
        for (int d = 0; d < D_; d += 4) {
            float4 cv = *(const float4*)&s_c[lane][d];
            cnl = fmaf(cv.x, cv.x, fmaf(cv.y, cv.y, fmaf(cv.z, cv.z, fmaf(cv.w, cv.w, cnl))));
        }
        cn2 = cnl * LOG2E;
    }

    // omega rows for this warp's 4 rows (lane = s), + hs into smem
    float om0, om1, om2, om3;
#pragma unroll
    for (int j = 0; j < 4; j++) {
        const int r = rows[j];
        float cd = 0.f;
#pragma unroll
        for (int d = 0; d < D_; d += 4) {
            float4 a = *(const float4*)&s_c[r][d];
            float4 b = *(const float4*)&s_c[lane][d];
            float dx = a.x - b.x, dy = a.y - b.y, dz = a.z - b.z, dw = a.w - b.w;
            cd = fmaf(dx, dx, fmaf(dy, dy, fmaf(dz, dz, fmaf(dw, dw, cd))));
        }
        float omv = ex2f(-cd * LOG2E);   // exp(-cd)
        if (j == 0) om0 = omv; else if (j == 1) om1 = omv;
        else if (j == 2) om2 = omv; else om3 = omv;
        float h = omv;
#pragma unroll
        for (int off = 16; off; off >>= 1)
            h += __shfl_xor_sync(0xffffffffu, h, off);
        if (lane == 0) s_hs[r] = h - 1.0f;   // remove diagonal exp(0)=1
    }

    float lacc = 0.f;   // per-lane, log2 domain: sum om * q*log2 q
    float eacc = 0.f;   // per-lane, log2 domain: sum hs_r * pb'*(log2 pb' + 1)

    int it = 0;
#pragma unroll 1
    for (int bt = blockIdx.x; bt < BT; bt += GRID_, it++) {
        const int buf = it & 1;
        const int btn = bt + GRID_;
        if (btn < BT) {
            unsigned a = (unsigned)__cvta_generic_to_shared(&s_m[buf ^ 1][tid]);
            unsigned b = (unsigned)__cvta_generic_to_shared(&s_p[buf ^ 1][tid]);
            cp_async16(a, (const float4*)(gm + (size_t)btn * 1024) + tid);
            cp_async16(b, (const float4*)(gp + (size_t)btn * 1024) + tid);
            cp_commit();
            asm volatile("cp.async.wait_group 1;");
        } else {
            asm volatile("cp.async.wait_group 0;");
        }
        if (tid < P_) s_w[buf][tid] = pw;
        __syncthreads();   // buf + s_hs visible; all warps done with prior pair loop
        if (btn < BT && tid < P_) pw = gw[(size_t)btn * P_ + tid];

        const float* smt = (const float*)s_m[buf];
        const float* spt = (const float*)s_p[buf];

        // ---- step 1: softmax via ex2; logit2 = 2*log2e*(m.c) - cn2 ----
        {
            const int p0 = wid, p1 = wid + 8;
            const int r = lane;
            float a0 = 0.f, a1 = 0.f;
#pragma unroll
            for (int d = 0; d < D_; d += 4) {
                float4 cv  = *(const float4*)&s_c[r][d];
                float4 mv0 = *(const float4*)&smt[p0 * D_ + d];
                float4 mv1 = *(const float4*)&smt[p1 * D_ + d];
                a0 = fmaf(mv0.x, cv.x, fmaf(mv0.y, cv.y, fmaf(mv0.z, cv.z, fmaf(mv0.w, cv.w, a0))));
                a1 = fmaf(mv1.x, cv.x, fmaf(mv1.y, cv.y, fmaf(mv1.z, cv.z, fmaf(mv1.w, cv.w, a1))));
            }
            float e0 = ex2f(fmaf(TWO_LOG2E, a0, -cn2));
            float e1 = ex2f(fmaf(TWO_LOG2E, a1, -cn2));
            float sm0 = e0, sm1 = e1;
#pragma unroll
            for (int off = 16; off; off >>= 1) {
                sm0 += __shfl_xor_sync(0xffffffffu, sm0, off);
                sm1 += __shfl_xor_sync(0xffffffffu, sm1, off);
            }
            s_sm[p0][lane] = e0 * __fdividef(s_w[buf][p0], sm0);
            s_sm[p1][lane] = e1 * __fdividef(s_w[buf][p1], sm1);
        }
        __syncthreads();

        // ---- step 3: p_bar' + per-lane row terms; rows {r0..r3} ----
        u64 prq[4];
        {
            float acc0[4] = {0.f,0.f,0.f,0.f};
            float acc1[4] = {0.f,0.f,0.f,0.f};
#pragma unroll
            for (int pp = 0; pp < P_; pp++) {
                float2 sp = *(const float2*)&spt[pp * K_ + 2 * lane];
#pragma unroll
                for (int j = 0; j < 4; j++) {
                    float g = s_sm[pp][rows[j]];
                    acc0[j] = fmaf(sp.x, g, acc0[j]);
                    acc1[j] = fmaf(sp.y, g, acc1[j]);
                }
            }
#pragma unroll
            for (int j = 0; j < 4; j++) {
                const int r = rows[j];
                float v = (lane < P_) ? s_sm[lane][r] : 0.f;
#pragma unroll
                for (int off = 16; off; off >>= 1)
                    v += __shfl_xor_sync(0xffffffffu, v, off);
                float tm = __fdividef(1.0f, v + 1e-6f);
                float pb0 = fmaf(acc0[j], tm, 1e-8f);   // pb' = pb + eps
                float pb1 = fmaf(acc1[j], tm, 1e-8f);
                s_pb[r][lane] = make_float2(pb0, pb1);
                prq[j] = pk2(pb0, pb1);
                float l0 = __log2f(pb0) + 1.0f;
                float l1 = __log2f(pb1) + 1.0f;
                eacc = fmaf(s_hs[r], fmaf(pb0, l0, pb1 * l1), eacc);   // per-lane
            }
        }
        __syncthreads();

        // ---- pair loop: 4 rolled branch-free segments, unroll 2;
        //      q = pb'_r + pb'_s via one packed add; omega via shfl ----
        {
#pragma unroll 2
            for (int s = r0 + 1; s <= r1; s++) {
                u64 ps2 = *(const u64*)&s_pb[s][lane];
                float q0, q1; upk2(add2(prq[0], ps2), q0, q1);
                float tt = fmaf(q0, __log2f(q0), q1 * __log2f(q1));
                lacc = fmaf(__shfl_sync(0xffffffffu, om0, s), tt, lacc);
            }
#pragma unroll 2
            for (int s = r1 + 1; s <= r2; s++) {
                u64 ps2 = *(const u64*)&s_pb[s][lane];
                float q0, q1; upk2(add2(prq[0], ps2), q0, q1);
                float tt = fmaf(q0, __log2f(q0), q1 * __log2f(q1));
                lacc = fmaf(__shfl_sync(0xffffffffu, om0, s), tt, lacc);
                upk2(add2(prq[1], ps2), q0, q1);
                tt = fmaf(q0, __log2f(q0), q1 * __log2f(q1));
                lacc = fmaf(__shfl_sync(0xffffffffu, om1, s), tt, lacc);
            }
#pragma unroll 2
            for (int s = r2 + 1; s <= r3; s++) {
                u64 ps2 = *(const u64*)&s_pb[s][lane];
                float q0, q1; upk2(add2(prq[0], ps2), q0, q1);
                float tt = fmaf(q0, __log2f(q0), q1 * __log2f(q1));
                lacc = fmaf(__shfl_sync(0xffffffffu, om0, s), tt, lacc);
                upk2(add2(prq[1], ps2), q0, q1);
                tt = fmaf(q0, __log2f(q0), q1 * __log2f(q1));
                lacc = fmaf(__shfl_sync(0xffffffffu, om1, s), tt, lacc);
                upk2(add2(prq[2], ps2), q0, q1);
                tt = fmaf(q0, __log2f(q0), q1 * __log2f(q1));
                lacc = fmaf(__shfl_sync(0xffffffffu, om2, s), tt, lacc);
            }
#pragma unroll 2
            for (int s = r3 + 1; s < R_; s++) {
                u64 ps2 = *(const u64*)&s_pb[s][lane];
                float q0, q1; upk2(add2(prq[0], ps2), q0, q1);
                float tt = fmaf(q0, __log2f(q0), q1 * __log2f(q1));
                lacc = fmaf(__shfl_sync(0xffffffffu, om0, s), tt, lacc);
                upk2(add2(prq[1], ps2), q0, q1);
                tt = fmaf(q0, __log2f(q0), q1 * __log2f(q1));
                lacc = fmaf(__shfl_sync(0xffffffffu, om1, s), tt, lacc);
                upk2(add2(prq[2], ps2), q0, q1);
                tt = fmaf(q0, __log2f(q0), q1 * __log2f(q1));
                lacc = fmaf(__shfl_sync(0xffffffffu, om2, s), tt, lacc);
                upk2(add2(prq[3], ps2), q0, q1);
                tt = fmaf(q0, __log2f(q0), q1 * __log2f(q1));
                lacc = fmaf(__shfl_sync(0xffffffffu, om3, s), tt, lacc);
            }
        }
    }

    // ---- final reduction; last CTA writes result and resets state ----
    float v = eacc - lacc;
#pragma unroll
    for (int off = 16; off; off >>= 1)
        v += __shfl_xor_sync(0xffffffffu, v, off);
    if (lane == 0) s_red[wid] = 0.5f * v * LN2;
    __syncthreads();
    if (tid == 0) {
        float a = 0.f;
#pragma unroll
        for (int i = 0; i < 8; i++) a += s_red[i];
        atomicAdd(&g_acc, (double)a);
        __threadfence();
        unsigned int ticket = atomicAdd(&g_done, 1u);
        if (ticket == gridDim.x - 1) {
            double total = *(volatile double*)&g_acc;
            gout[0] = (float)(total / (496.0 + 1e-8));
            // reset for next graph replay (deterministic: last CTA only)
            g_acc = 0.0;
            __threadfence();
            *(volatile unsigned int*)&g_done = 0u;
        }
    }
}

extern "C" void kernel_launch(void* const* d_in, const int* in_sizes, int n_in,
                              void* d_out, int out_size) {
    const float* m = (const float*)d_in[0];
    const float* w = (const float*)d_in[1];
    const float* p = (const float*)d_in[2];
    const float* c = (const float*)d_in[3];
    float* out = (float*)d_out;
    (void)in_sizes; (void)n_in; (void)out_size;

    sheaf_kernel<<<GRID_, 256>>>(m, w, p, c, out);
}

// round 17
// speedup vs baseline: 1.3409x; 1.3409x over previous
#include <cuda_runtime.h>

// SheafLoss: B=4 T=1024 P=16 D=64 R=32 K=64, TAU=1
// d_in[0]=m (B,T,P,D) f32, d_in[1]=w (B,T,P) f32,
// d_in[2]=p (B,T,P,K) f32, d_in[3]=patch_centers (R,D) f32
// out: scalar f32

#define BT    4096
#define P_    16
#define D_    64
#define R_    32
#define K_    64
#define GRID_ 912          // 152 SMs x 6 CTAs: one persistent wave
#define LN2   0.6931471805599453f
#define TWO_LOG2E 2.8853900817779268f   // 2*log2(e)
#define LOG2E 1.4426950408889634f

typedef unsigned long long u64;

__device__ double g_acc;
__device__ unsigned int g_done;
__device__ float  g_omega[R_ * R_];
__device__ float  g_cn2[R_];    // |c_r|^2 * log2(e)
__device__ float  g_hs[R_];     // hs[r] = sum_{s != r} omega[r][s]

__device__ __forceinline__ void cp_async16(unsigned saddr, const void* gaddr) {
    asm volatile("cp.async.ca.shared.global [%0], [%1], 16;" :: "r"(saddr), "l"(gaddr));
}
__device__ __forceinline__ void cp_commit() {
    asm volatile("cp.async.commit_group;");
}
__device__ __forceinline__ u64 pk2(float x, float y) {
    u64 r; asm("mov.b64 %0, {%1, %2};" : "=l"(r) : "f"(x), "f"(y)); return r;
}
__device__ __forceinline__ void upk2(u64 v, float& x, float& y) {
    asm("mov.b64 {%0, %1}, %2;" : "=f"(x), "=f"(y) : "l"(v));
}
__device__ __forceinline__ u64 add2(u64 a, u64 b) {
    u64 r; asm("add.rn.f32x2 %0, %1, %2;" : "=l"(r) : "l"(a), "l"(b)); return r;
}
__device__ __forceinline__ float ex2f(float x) {
    float r; asm("ex2.approx.ftz.f32 %0, %1;" : "=f"(r) : "f"(x)); return r;
}

// ---------------------------------------------------------------------------
// Setup: 4 blocks x 256 threads; block b handles rows [8b, 8b+8).
// ---------------------------------------------------------------------------
__global__ void __launch_bounds__(256) sheaf_setup_kernel(const float* __restrict__ gc) {
    __shared__ float sc[R_][D_ + 1];
    const int tid = threadIdx.x;
    for (int i = tid; i < R_ * D_; i += 256) sc[i >> 6][i & 63] = gc[i];
    __syncthreads();
    const int r = blockIdx.x * 8 + (tid >> 5);
    const int s = tid & 31;
    float cd = 0.f;
#pragma unroll 8
    for (int d = 0; d < D_; d++) {
        float df = sc[r][d] - sc[s][d];
        cd = fmaf(df, df, cd);
    }
    float omv = expf(-cd);
    g_omega[r * R_ + s] = omv;
    float hs = omv;
#pragma unroll
    for (int off = 16; off; off >>= 1)
        hs += __shfl_xor_sync(0xffffffffu, hs, off);
    if (s == 0) g_hs[r] = hs - 1.0f;
    float t = sc[r][s] * sc[r][s] + sc[r][s + 32] * sc[r][s + 32];
#pragma unroll
    for (int off = 16; off; off >>= 1)
        t += __shfl_xor_sync(0xffffffffu, t, off);
    if (s == 1) g_cn2[r] = t * LOG2E;
    if (r == 0 && s == 2) { g_acc = 0.0; g_done = 0u; }
}

// ---------------------------------------------------------------------------
// Main: persistent grid (912 CTAs), grid-stride over tiles, 256 threads,
// 6 CTAs/SM, double-buffered m/p. Lane owns k-slice (2l, 2l+1); warp rows
// {w, 15-w, 16+w, 31-w}; omega register-resident via shfl.
// Algebra: s_pb holds p_bar + 1e-8. With q = pb'_r + pb'_s:
//   sum_k m*log2(m+eps) = 0.5*sum q*log2 q - 0.5*(S'_r + S'_s)
// pair loop accumulates om * sum q*log2 q per-lane; rows carry
// hs_r * sum_lane pb'*(log2 pb' + 1). loss(log2) = 0.5*(eacc - lacc) * LN2.
// ---------------------------------------------------------------------------
__global__ void __launch_bounds__(256, 6) sheaf_kernel(
    const float* __restrict__ gm,
    const float* __restrict__ gw,
    const float* __restrict__ gp,
    const float* __restrict__ gc,
    float* __restrict__ gout)
{
    __shared__ float  s_c[R_][68];        // centers row-major, 16B rows
    __shared__ float4 s_m[2][256];        // double-buffered m tile
    __shared__ float4 s_p[2][256];        // double-buffered p tile
    __shared__ float  s_w[2][P_];
    __shared__ float  s_sm[P_][R_ + 1];
    __shared__ float2 s_pb[R_][R_];       // [r][lane] = (pb'[2l], pb'[2l+1])
    __shared__ float  s_cn2[R_];
    __shared__ float  s_hs[R_];
    __shared__ float  s_red[8];

    const int tid  = threadIdx.x;
    const int lane = tid & 31;
    const int wid  = tid >> 5;

    const int r0 = wid, r1 = 15 - wid, r2 = 16 + wid, r3 = 31 - wid;

    // per-CTA constants (amortized over ~4.5 tiles)
    for (int i = tid; i < R_ * D_; i += 256) s_c[i >> 6][i & 63] = gc[i];
    if (tid < R_) { s_cn2[tid] = g_cn2[tid]; s_hs[tid] = g_hs[tid]; }

    // tile-invariant omega rows, register-resident
    const float om0 = g_omega[r0 * R_ + lane];
    const float om1 = g_omega[r1 * R_ + lane];
    const float om2 = g_omega[r2 * R_ + lane];
    const float om3 = g_omega[r3 * R_ + lane];

    // prologue: async-copy first tile into buffer 0
    {
        const int bt = blockIdx.x;
        unsigned a = (unsigned)__cvta_generic_to_shared(&s_m[0][tid]);
        unsigned b = (unsigned)__cvta_generic_to_shared(&s_p[0][tid]);
        cp_async16(a, (const float4*)(gm + (size_t)bt * 1024) + tid);
        cp_async16(b, (const float4*)(gp + (size_t)bt * 1024) + tid);
        cp_commit();
    }
    float pw = (tid < P_) ? gw[(size_t)blockIdx.x * P_ + tid] : 0.f;

    float lacc = 0.f;   // per-lane, log2 domain: sum om * q*log2 q
    float eacc = 0.f;   // per-lane, log2 domain: sum hs_r * pb'*(log2 pb' + 1)

    int it = 0;
#pragma unroll 1
    for (int bt = blockIdx.x; bt < BT; bt += GRID_, it++) {
        const int buf = it & 1;
        const int btn = bt + GRID_;
        if (btn < BT) {
            unsigned a = (unsigned)__cvta_generic_to_shared(&s_m[buf ^ 1][tid]);
            unsigned b = (unsigned)__cvta_generic_to_shared(&s_p[buf ^ 1][tid]);
            cp_async16(a, (const float4*)(gm + (size_t)btn * 1024) + tid);
            cp_async16(b, (const float4*)(gp + (size_t)btn * 1024) + tid);
            cp_commit();
            asm volatile("cp.async.wait_group 1;");
        } else {
            asm volatile("cp.async.wait_group 0;");
        }
        if (tid < P_) s_w[buf][tid] = pw;
        __syncthreads();   // buf visible; all warps done with previous pair loop
        if (btn < BT && tid < P_) pw = gw[(size_t)btn * P_ + tid];

        const float* smt = (const float*)s_m[buf];
        const float* spt = (const float*)s_p[buf];

        // ---- step 1: softmax via raw ex2; logit2 = 2*log2e*(m.c) - cn2 ----
        {
            const int p0 = wid, p1 = wid + 8;
            const int r = lane;
            float a0 = 0.f, a1 = 0.f;
#pragma unroll
            for (int d = 0; d < D_; d += 4) {
                float4 cv  = *(const float4*)&s_c[r][d];
                float4 mv0 = *(const float4*)&smt[p0 * D_ + d];
                float4 mv1 = *(const float4*)&smt[p1 * D_ + d];
                a0 = fmaf(mv0.x, cv.x, fmaf(mv0.y, cv.y, fmaf(mv0.z, cv.z, fmaf(mv0.w, cv.w, a0))));
                a1 = fmaf(mv1.x, cv.x, fmaf(mv1.y, cv.y, fmaf(mv1.z, cv.z, fmaf(mv1.w, cv.w, a1))));
            }
            const float cn2 = s_cn2[r];
            float e0 = ex2f(fmaf(TWO_LOG2E, a0, -cn2));
            float e1 = ex2f(fmaf(TWO_LOG2E, a1, -cn2));
            float sm0 = e0, sm1 = e1;
#pragma unroll
            for (int off = 16; off; off >>= 1) {
                sm0 += __shfl_xor_sync(0xffffffffu, sm0, off);
                sm1 += __shfl_xor_sync(0xffffffffu, sm1, off);
            }
            s_sm[p0][lane] = e0 * __fdividef(s_w[buf][p0], sm0);
            s_sm[p1][lane] = e1 * __fdividef(s_w[buf][p1], sm1);
        }
        __syncthreads();

        // ---- step 3: p_bar' + per-lane row terms; rows {r0..r3} ----
        u64 prq[4];
        {
            const int rows[4] = { r0, r1, r2, r3 };
            float acc0[4] = {0.f,0.f,0.f,0.f};
            float acc1[4] = {0.f,0.f,0.f,0.f};
#pragma unroll
            for (int pp = 0; pp < P_; pp++) {
                float2 sp = *(const float2*)&spt[pp * K_ + 2 * lane];
#pragma unroll
                for (int j = 0; j < 4; j++) {
                    float g = s_sm[pp][rows[j]];
                    acc0[j] = fmaf(sp.x, g, acc0[j]);
                    acc1[j] = fmaf(sp.y, g, acc1[j]);
                }
            }
#pragma unroll
            for (int j = 0; j < 4; j++) {
                const int r = rows[j];
                float v = (lane < P_) ? s_sm[lane][r] : 0.f;
#pragma unroll
                for (int off = 16; off; off >>= 1)
                    v += __shfl_xor_sync(0xffffffffu, v, off);
                float tm = __fdividef(1.0f, v + 1e-6f);
                float pb0 = fmaf(acc0[j], tm, 1e-8f);   // pb' = pb + eps
                float pb1 = fmaf(acc1[j], tm, 1e-8f);
                s_pb[r][lane] = make_float2(pb0, pb1);
                prq[j] = pk2(pb0, pb1);
                float l0 = __log2f(pb0) + 1.0f;
                float l1 = __log2f(pb1) + 1.0f;
                eacc = fmaf(s_hs[r], fmaf(pb0, l0, pb1 * l1), eacc);   // per-lane
            }
        }
        __syncthreads();

        // ---- pair loop: 4 rolled branch-free segments; q = pb'_r + pb'_s
        //      via one packed add; omega from registers via shfl. ----
        {
            for (int s = r0 + 1; s <= r1; s++) {
                u64 ps2 = *(const u64*)&s_pb[s][lane];
                float q0, q1; upk2(add2(prq[0], ps2), q0, q1);
                float tt = fmaf(q0, __log2f(q0), q1 * __log2f(q1));
                lacc = fmaf(__shfl_sync(0xffffffffu, om0, s), tt, lacc);
            }
            for (int s = r1 + 1; s <= r2; s++) {
                u64 ps2 = *(const u64*)&s_pb[s][lane];
                float q0, q1; upk2(add2(prq[0], ps2), q0, q1);
                float tt = fmaf(q0, __log2f(q0), q1 * __log2f(q1));
                lacc = fmaf(__shfl_sync(0xffffffffu, om0, s), tt, lacc);
                upk2(add2(prq[1], ps2), q0, q1);
                tt = fmaf(q0, __log2f(q0), q1 * __log2f(q1));
                lacc = fmaf(__shfl_sync(0xffffffffu, om1, s), tt, lacc);
            }
            for (int s = r2 + 1; s <= r3; s++) {
                u64 ps2 = *(const u64*)&s_pb[s][lane];
                float q0, q1; upk2(add2(prq[0], ps2), q0, q1);
                float tt = fmaf(q0, __log2f(q0), q1 * __log2f(q1));
                lacc = fmaf(__shfl_sync(0xffffffffu, om0, s), tt, lacc);
                upk2(add2(prq[1], ps2), q0, q1);
                tt = fmaf(q0, __log2f(q0), q1 * __log2f(q1));
                lacc = fmaf(__shfl_sync(0xffffffffu, om1, s), tt, lacc);
                upk2(add2(prq[2], ps2), q0, q1);
                tt = fmaf(q0, __log2f(q0), q1 * __log2f(q1));
                lacc = fmaf(__shfl_sync(0xffffffffu, om2, s), tt, lacc);
            }
            for (int s = r3 + 1; s < R_; s++) {
                u64 ps2 = *(const u64*)&s_pb[s][lane];
                float q0, q1; upk2(add2(prq[0], ps2), q0, q1);
                float tt = fmaf(q0, __log2f(q0), q1 * __log2f(q1));
                lacc = fmaf(__shfl_sync(0xffffffffu, om0, s), tt, lacc);
                upk2(add2(prq[1], ps2), q0, q1);
                tt = fmaf(q0, __log2f(q0), q1 * __log2f(q1));
                lacc = fmaf(__shfl_sync(0xffffffffu, om1, s), tt, lacc);
                upk2(add2(prq[2], ps2), q0, q1);
                tt = fmaf(q0, __log2f(q0), q1 * __log2f(q1));
                lacc = fmaf(__shfl_sync(0xffffffffu, om2, s), tt, lacc);
                upk2(add2(prq[3], ps2), q0, q1);
                tt = fmaf(q0, __log2f(q0), q1 * __log2f(q1));
                lacc = fmaf(__shfl_sync(0xffffffffu, om3, s), tt, lacc);
            }
        }
    }

    // ---- final reduction: loss(log2) = 0.5*(eacc - lacc), one butterfly ----
    float v = eacc - lacc;
#pragma unroll
    for (int off = 16; off; off >>= 1)
        v += __shfl_xor_sync(0xffffffffu, v, off);
    if (lane == 0) s_red[wid] = 0.5f * v * LN2;
    __syncthreads();
    if (tid == 0) {
        float a = 0.f;
#pragma unroll
        for (int i = 0; i < 8; i++) a += s_red[i];
        atomicAdd(&g_acc, (double)a);
        __threadfence();
        unsigned int ticket = atomicAdd(&g_done, 1u);
        if (ticket == gridDim.x - 1) {
            double total = *(volatile double*)&g_acc;
            gout[0] = (float)(total / (496.0 + 1e-8));
        }
    }
}

extern "C" void kernel_launch(void* const* d_in, const int* in_sizes, int n_in,
                              void* d_out, int out_size) {
    const float* m = (const float*)d_in[0];
    const float* w = (const float*)d_in[1];
    const float* p = (const float*)d_in[2];
    const float* c = (const float*)d_in[3];
    float* out = (float*)d_out;
    (void)in_sizes; (void)n_in; (void)out_size;

    sheaf_setup_kernel<<<4, 256>>>(c);
    sheaf_kernel<<<GRID_, 256>>>(m, w, p, c, out);
}